// round 1
// baseline (speedup 1.0000x reference)
#include <cuda_runtime.h>
#include <math.h>

// ---------------- problem constants ----------------
#define DMODEL 1024
#define HEADS  16
#define DH     64
#define B_LAT  9
#define B_X    8
#define N_KV   256
#define N_Q    64
#define CHUNK  (N_KV + N_Q)          // 320
#define KV_ROWS (B_X * CHUNK)        // 2560
#define Q_ROWS  (B_LAT * N_Q)        // 576
#define SCALE   0.125f               // DH^-0.5 applied to Q

// ---------------- scratch (no allocations allowed) ----------------
__device__ float g_kvin[KV_ROWS * DMODEL];        // LN'd concat input for KV gemm
__device__ float g_latn[Q_ROWS * DMODEL];         // LN'd latents (Q gemm input)
__device__ float g_Q   [Q_ROWS * DMODEL];         // Q = latn @ Wq
__device__ float g_KV  [KV_ROWS * 2 * DMODEL];    // [K | V]
__device__ float g_attn[Q_ROWS * DMODEL];         // attention output (heads merged)
__device__ float g_Po[8 * HEADS * N_Q * DH];      // split-KV partials for batch 8
__device__ float g_Pm[8 * HEADS * N_Q];
__device__ float g_Pl[8 * HEADS * N_Q];

// ---------------- LayerNorm ----------------
__device__ __forceinline__ void ln_row(const float* __restrict__ xr,
                                       const float* __restrict__ g,
                                       const float* __restrict__ b,
                                       float* __restrict__ out0,
                                       float* __restrict__ out1) {
    int t = threadIdx.x;                       // 256 threads, 1024 elems
    const float4* x4 = (const float4*)xr;
    float4 v = x4[t];
    float s  = v.x + v.y + v.z + v.w;
    float ss = v.x*v.x + v.y*v.y + v.z*v.z + v.w*v.w;
    #pragma unroll
    for (int o = 16; o; o >>= 1) {
        s  += __shfl_xor_sync(0xffffffffu, s,  o);
        ss += __shfl_xor_sync(0xffffffffu, ss, o);
    }
    __shared__ float sb[8], ssb[8];
    if ((t & 31) == 0) { sb[t >> 5] = s; ssb[t >> 5] = ss; }
    __syncthreads();
    float S = 0.f, SS = 0.f;
    #pragma unroll
    for (int i = 0; i < 8; i++) { S += sb[i]; SS += ssb[i]; }
    float mean = S * (1.0f / DMODEL);
    float var  = SS * (1.0f / DMODEL) - mean * mean;
    float rstd = rsqrtf(var + 1e-5f);
    float4 gg = ((const float4*)g)[t];
    float4 bb = ((const float4*)b)[t];
    float4 o;
    o.x = (v.x - mean) * rstd * gg.x + bb.x;
    o.y = (v.y - mean) * rstd * gg.y + bb.y;
    o.z = (v.z - mean) * rstd * gg.z + bb.z;
    o.w = (v.w - mean) * rstd * gg.w + bb.w;
    ((float4*)out0)[t] = o;
    if (out1) ((float4*)out1)[t] = o;
}

__global__ __launch_bounds__(256) void ln_x_kernel(const float* __restrict__ x,
                                                   const float* __restrict__ g,
                                                   const float* __restrict__ b) {
    int row = blockIdx.x;               // 0..2047
    int batch = row >> 8;               // /256
    int r = row & 255;
    ln_row(x + (size_t)row * DMODEL, g, b,
           g_kvin + (size_t)(batch * CHUNK + r) * DMODEL, nullptr);
}

__global__ __launch_bounds__(256) void ln_lat_kernel(const float* __restrict__ lat,
                                                     const float* __restrict__ g,
                                                     const float* __restrict__ b) {
    int row = blockIdx.x;               // 0..575
    int batch = row >> 6;               // /64
    int q = row & 63;
    float* out1 = (batch < B_X)
        ? (g_kvin + (size_t)(batch * CHUNK + N_KV + q) * DMODEL) : nullptr;
    ln_row(lat + (size_t)row * DMODEL, g, b,
           g_latn + (size_t)row * DMODEL, out1);
}

// ---------------- fp32 tiled GEMM: C[M,N] = A[M,K] @ B[K,N] ----------------
// BM=128, BN=64, BK=16, 256 threads, 8x4 microtile. M guarded; N,K multiples of tile.
#define GBM 128
#define GBN 64
#define GBK 16
__global__ __launch_bounds__(256) void gemm_kernel(const float* __restrict__ A,
                                                   const float* __restrict__ B,
                                                   float* __restrict__ C,
                                                   int M, int N, int K) {
    __shared__ float As[GBK][GBM + 4];   // [k][m], padded
    __shared__ float Bs[GBK][GBN];       // [k][n]
    int t  = threadIdx.x;
    int tx = t & 15;            // n-group
    int ty = t >> 4;            // m-group
    int row0 = blockIdx.y * GBM;
    int col0 = blockIdx.x * GBN;

    int arow = t >> 2;                  // 0..63
    int akc  = (t & 3) << 2;            // 0,4,8,12
    int brow = t >> 4;                  // 0..15
    int bcol = (t & 15) << 2;           // 0..60

    float acc[8][4];
    #pragma unroll
    for (int i = 0; i < 8; i++)
        #pragma unroll
        for (int j = 0; j < 4; j++) acc[i][j] = 0.f;

    for (int k0 = 0; k0 < K; k0 += GBK) {
        #pragma unroll
        for (int h = 0; h < 2; h++) {
            int r = arow + h * 64;
            float4 av = make_float4(0.f, 0.f, 0.f, 0.f);
            if (row0 + r < M)
                av = *(const float4*)(A + (size_t)(row0 + r) * K + k0 + akc);
            As[akc + 0][r] = av.x;
            As[akc + 1][r] = av.y;
            As[akc + 2][r] = av.z;
            As[akc + 3][r] = av.w;
        }
        float4 bv = *(const float4*)(B + (size_t)(k0 + brow) * N + col0 + bcol);
        *(float4*)&Bs[brow][bcol] = bv;
        __syncthreads();

        #pragma unroll
        for (int k = 0; k < GBK; k++) {
            float4 a0 = *(const float4*)&As[k][ty * 8 + 0];
            float4 a1 = *(const float4*)&As[k][ty * 8 + 4];
            float4 b4 = *(const float4*)&Bs[k][tx * 4];
            float a[8] = {a0.x, a0.y, a0.z, a0.w, a1.x, a1.y, a1.z, a1.w};
            float bq[4] = {b4.x, b4.y, b4.z, b4.w};
            #pragma unroll
            for (int i = 0; i < 8; i++)
                #pragma unroll
                for (int j = 0; j < 4; j++)
                    acc[i][j] = fmaf(a[i], bq[j], acc[i][j]);
        }
        __syncthreads();
    }

    #pragma unroll
    for (int i = 0; i < 8; i++) {
        int r = row0 + ty * 8 + i;
        if (r < M) {
            float4 o = make_float4(acc[i][0], acc[i][1], acc[i][2], acc[i][3]);
            *(float4*)(C + (size_t)r * N + col0 + tx * 4) = o;
        }
    }
}

// ---------------- attention ----------------
// grid: (16 jobs, 16 heads). job<8: diagonal block (q-batch j, kv-chunk j), writes
// normalized output. job>=8: split-KV chunk (j-8) for q-batch 8, writes partials.
// 256 threads = 8 warps; warp w owns query rows w*8..w*8+7.
__global__ __launch_bounds__(256) void attn_kernel() {
    extern __shared__ float sm[];
    float* Qs = sm;                      // 64*64
    float* Ks = Qs + 64 * 64;            // 64*68 (padded)
    float* Vs = Ks + 64 * 68;            // 64*64
    float* Ps = Vs + 64 * 64;            // 64*64

    int job = blockIdx.x;
    int h   = blockIdx.y;
    int t = threadIdx.x;
    int lane = t & 31, w = t >> 5;
    bool diag = (job < 8);
    int qb = diag ? job : 8;
    int kc = diag ? job : (job - 8);

    // load Q tile (pre-scaled)
    for (int i = t; i < 64 * 16; i += 256) {
        int r = i >> 4, c4 = (i & 15) << 2;
        float4 v = *(const float4*)(g_Q + (size_t)(qb * 64 + r) * DMODEL + h * DH + c4);
        v.x *= SCALE; v.y *= SCALE; v.z *= SCALE; v.w *= SCALE;
        *(float4*)&Qs[r * 64 + c4] = v;
    }

    float m[8], l[8], o0[8], o1[8];
    #pragma unroll
    for (int rr = 0; rr < 8; rr++) { m[rr] = -INFINITY; l[rr] = 0.f; o0[rr] = 0.f; o1[rr] = 0.f; }

    for (int tt = 0; tt < CHUNK / 64; tt++) {          // 5 key tiles of 64
        int base = kc * CHUNK + tt * 64;
        // load K (padded rows) and V
        for (int i = t; i < 64 * 16; i += 256) {
            int r = i >> 4, c4 = (i & 15) << 2;
            const float* src = g_KV + (size_t)(base + r) * (2 * DMODEL) + h * DH;
            float4 kk = *(const float4*)(src + c4);
            *(float4*)&Ks[r * 68 + c4] = kk;
            float4 vv = *(const float4*)(src + DMODEL + c4);
            *(float4*)&Vs[r * 64 + c4] = vv;
        }
        __syncthreads();

        // scores: s[rr] for keys (lane, lane+32), K held in regs across rows
        float s0[8], s1[8];
        #pragma unroll
        for (int rr = 0; rr < 8; rr++) { s0[rr] = 0.f; s1[rr] = 0.f; }
        const float* k0p = &Ks[lane * 68];
        const float* k1p = &Ks[(lane + 32) * 68];
        #pragma unroll
        for (int d4 = 0; d4 < 16; d4++) {
            float4 ka = *(const float4*)(k0p + d4 * 4);
            float4 kb = *(const float4*)(k1p + d4 * 4);
            #pragma unroll
            for (int rr = 0; rr < 8; rr++) {
                float4 q4 = *(const float4*)&Qs[(w * 8 + rr) * 64 + d4 * 4];
                s0[rr] = fmaf(q4.x, ka.x, s0[rr]); s0[rr] = fmaf(q4.y, ka.y, s0[rr]);
                s0[rr] = fmaf(q4.z, ka.z, s0[rr]); s0[rr] = fmaf(q4.w, ka.w, s0[rr]);
                s1[rr] = fmaf(q4.x, kb.x, s1[rr]); s1[rr] = fmaf(q4.y, kb.y, s1[rr]);
                s1[rr] = fmaf(q4.z, kb.z, s1[rr]); s1[rr] = fmaf(q4.w, kb.w, s1[rr]);
            }
        }

        // online softmax update per row
        #pragma unroll
        for (int rr = 0; rr < 8; rr++) {
            int r = w * 8 + rr;
            float mt = fmaxf(s0[rr], s1[rr]);
            #pragma unroll
            for (int o = 16; o; o >>= 1) mt = fmaxf(mt, __shfl_xor_sync(0xffffffffu, mt, o));
            float mn = fmaxf(m[rr], mt);
            float corr = __expf(m[rr] - mn);
            float p0 = __expf(s0[rr] - mn);
            float p1 = __expf(s1[rr] - mn);
            Ps[r * 64 + lane]      = p0;
            Ps[r * 64 + lane + 32] = p1;
            float ps = p0 + p1;
            #pragma unroll
            for (int o = 16; o; o >>= 1) ps += __shfl_xor_sync(0xffffffffu, ps, o);
            l[rr] = l[rr] * corr + ps;
            m[rr] = mn;
            o0[rr] *= corr;
            o1[rr] *= corr;
        }
        __syncwarp();

        // PV: V held in regs across rows, P read as float4 broadcast
        #pragma unroll
        for (int k4 = 0; k4 < 16; k4++) {
            float va[4], vb[4];
            #pragma unroll
            for (int kk = 0; kk < 4; kk++) {
                va[kk] = Vs[(k4 * 4 + kk) * 64 + lane];
                vb[kk] = Vs[(k4 * 4 + kk) * 64 + lane + 32];
            }
            #pragma unroll
            for (int rr = 0; rr < 8; rr++) {
                float4 p4 = *(const float4*)&Ps[(w * 8 + rr) * 64 + k4 * 4];
                o0[rr] = fmaf(p4.x, va[0], o0[rr]); o0[rr] = fmaf(p4.y, va[1], o0[rr]);
                o0[rr] = fmaf(p4.z, va[2], o0[rr]); o0[rr] = fmaf(p4.w, va[3], o0[rr]);
                o1[rr] = fmaf(p4.x, vb[0], o1[rr]); o1[rr] = fmaf(p4.y, vb[1], o1[rr]);
                o1[rr] = fmaf(p4.z, vb[2], o1[rr]); o1[rr] = fmaf(p4.w, vb[3], o1[rr]);
            }
        }
        __syncthreads();
    }

    if (diag) {
        #pragma unroll
        for (int rr = 0; rr < 8; rr++) {
            int r = w * 8 + rr;
            float inv = 1.f / l[rr];
            float* dst = g_attn + (size_t)(qb * 64 + r) * DMODEL + h * DH;
            dst[lane]      = o0[rr] * inv;
            dst[lane + 32] = o1[rr] * inv;
        }
    } else {
        #pragma unroll
        for (int rr = 0; rr < 8; rr++) {
            int r = w * 8 + rr;
            float* dst = g_Po + (size_t)((kc * HEADS + h) * N_Q + r) * DH;
            dst[lane]      = o0[rr];
            dst[lane + 32] = o1[rr];
            if (lane == 0) {
                g_Pm[(kc * HEADS + h) * N_Q + r] = m[rr];
                g_Pl[(kc * HEADS + h) * N_Q + r] = l[rr];
            }
        }
    }
}

// combine split-KV partials for batch 8. grid (16 heads, 64 rows), 64 threads.
__global__ __launch_bounds__(64) void attn_reduce_kernel() {
    int h = blockIdx.x, r = blockIdx.y, d = threadIdx.x;
    float mx = -INFINITY;
    #pragma unroll
    for (int c = 0; c < 8; c++)
        mx = fmaxf(mx, g_Pm[(c * HEADS + h) * N_Q + r]);
    float lsum = 0.f, acc = 0.f;
    #pragma unroll
    for (int c = 0; c < 8; c++) {
        float wgt = __expf(g_Pm[(c * HEADS + h) * N_Q + r] - mx);
        lsum += g_Pl[(c * HEADS + h) * N_Q + r] * wgt;
        acc = fmaf(g_Po[(size_t)((c * HEADS + h) * N_Q + r) * DH + d], wgt, acc);
    }
    g_attn[(size_t)(8 * 64 + r) * DMODEL + h * DH + d] = acc / lsum;
}

// ---------------- launch ----------------
extern "C" void kernel_launch(void* const* d_in, const int* in_sizes, int n_in,
                              void* d_out, int out_size) {
    const float* x    = (const float*)d_in[0];
    const float* lat  = (const float*)d_in[1];
    const float* g1   = (const float*)d_in[2];
    const float* b1   = (const float*)d_in[3];
    const float* g2   = (const float*)d_in[4];
    const float* b2   = (const float*)d_in[5];
    const float* Wq   = (const float*)d_in[6];
    const float* Wkv  = (const float*)d_in[7];
    const float* Wout = (const float*)d_in[8];
    float* out = (float*)d_out;

    void *p_latn, *p_kvin, *p_Q, *p_KV, *p_attn;
    cudaGetSymbolAddress(&p_latn, g_latn);
    cudaGetSymbolAddress(&p_kvin, g_kvin);
    cudaGetSymbolAddress(&p_Q,    g_Q);
    cudaGetSymbolAddress(&p_KV,   g_KV);
    cudaGetSymbolAddress(&p_attn, g_attn);

    int attn_smem = (64 * 64 + 64 * 68 + 64 * 64 + 64 * 64) * (int)sizeof(float);
    cudaFuncSetAttribute(attn_kernel, cudaFuncAttributeMaxDynamicSharedMemorySize, attn_smem);

    ln_x_kernel<<<B_X * N_KV, 256>>>(x, g1, b1);
    ln_lat_kernel<<<Q_ROWS, 256>>>(lat, g2, b2);

    // Q = latn @ Wq : (576 x 1024) @ (1024 x 1024)
    gemm_kernel<<<dim3(DMODEL / GBN, (Q_ROWS + GBM - 1) / GBM), 256>>>(
        (const float*)p_latn, Wq, (float*)p_Q, Q_ROWS, DMODEL, DMODEL);

    // KV = kvin @ Wkv : (2560 x 1024) @ (1024 x 2048)
    gemm_kernel<<<dim3(2 * DMODEL / GBN, KV_ROWS / GBM), 256>>>(
        (const float*)p_kvin, Wkv, (float*)p_KV, KV_ROWS, 2 * DMODEL, DMODEL);

    attn_kernel<<<dim3(16, HEADS), 256, attn_smem>>>();
    attn_reduce_kernel<<<dim3(HEADS, N_Q), 64>>>();

    // out = attn @ Wout : (576 x 1024) @ (1024 x 1024)
    gemm_kernel<<<dim3(DMODEL / GBN, (Q_ROWS + GBM - 1) / GBM), 256>>>(
        (const float*)p_attn, Wout, out, Q_ROWS, DMODEL, DMODEL);

    (void)in_sizes; (void)n_in; (void)out_size;
}

// round 7
// speedup vs baseline: 1.6444x; 1.6444x over previous
#include <cuda_runtime.h>
#include <cuda_bf16.h>
#include <math.h>

// ---------------- problem constants ----------------
#define DMODEL 1024
#define HEADS  16
#define DH     64
#define B_LAT  9
#define B_X    8
#define N_KV   256
#define N_Q    64
#define CHUNK  (N_KV + N_Q)          // 320
#define KV_ROWS (B_X * CHUNK)        // 2560
#define Q_ROWS  (B_LAT * N_Q)        // 576
#define SCALE   0.125f               // DH^-0.5 applied to Q

// ---------------- scratch (no allocations allowed) ----------------
__device__ float g_kvin[KV_ROWS * DMODEL];        // LN'd concat input for KV gemm
__device__ float g_latn[Q_ROWS * DMODEL];         // LN'd latents (Q gemm input)
__device__ float g_Q   [Q_ROWS * DMODEL];         // Q = latn @ Wq
__device__ float g_KV  [KV_ROWS * 2 * DMODEL];    // [K | V]
__device__ float g_attn[Q_ROWS * DMODEL];         // attention output (heads merged)
__device__ float g_Po[8 * HEADS * N_Q * DH];      // split-KV partials for batch 8
__device__ float g_Pm[8 * HEADS * N_Q];
__device__ float g_Pl[8 * HEADS * N_Q];

// ---------------- LayerNorm ----------------
__device__ __forceinline__ void ln_row(const float* __restrict__ xr,
                                       const float* __restrict__ g,
                                       const float* __restrict__ b,
                                       float* __restrict__ out0,
                                       float* __restrict__ out1) {
    int t = threadIdx.x;                       // 256 threads, 1024 elems
    const float4* x4 = (const float4*)xr;
    float4 v = x4[t];
    float s  = v.x + v.y + v.z + v.w;
    float ss = v.x*v.x + v.y*v.y + v.z*v.z + v.w*v.w;
    #pragma unroll
    for (int o = 16; o; o >>= 1) {
        s  += __shfl_xor_sync(0xffffffffu, s,  o);
        ss += __shfl_xor_sync(0xffffffffu, ss, o);
    }
    __shared__ float sb[8], ssb[8];
    if ((t & 31) == 0) { sb[t >> 5] = s; ssb[t >> 5] = ss; }
    __syncthreads();
    float S = 0.f, SS = 0.f;
    #pragma unroll
    for (int i = 0; i < 8; i++) { S += sb[i]; SS += ssb[i]; }
    float mean = S * (1.0f / DMODEL);
    float var  = SS * (1.0f / DMODEL) - mean * mean;
    float rstd = rsqrtf(var + 1e-5f);
    float4 gg = ((const float4*)g)[t];
    float4 bb = ((const float4*)b)[t];
    float4 o;
    o.x = (v.x - mean) * rstd * gg.x + bb.x;
    o.y = (v.y - mean) * rstd * gg.y + bb.y;
    o.z = (v.z - mean) * rstd * gg.z + bb.z;
    o.w = (v.w - mean) * rstd * gg.w + bb.w;
    ((float4*)out0)[t] = o;
    if (out1) ((float4*)out1)[t] = o;
}

__global__ __launch_bounds__(256) void ln_x_kernel(const float* __restrict__ x,
                                                   const float* __restrict__ g,
                                                   const float* __restrict__ b) {
    int row = blockIdx.x;               // 0..2047
    int batch = row >> 8;               // /256
    int r = row & 255;
    ln_row(x + (size_t)row * DMODEL, g, b,
           g_kvin + (size_t)(batch * CHUNK + r) * DMODEL, nullptr);
}

__global__ __launch_bounds__(256) void ln_lat_kernel(const float* __restrict__ lat,
                                                     const float* __restrict__ g,
                                                     const float* __restrict__ b) {
    int row = blockIdx.x;               // 0..575
    int batch = row >> 6;               // /64
    int q = row & 63;
    float* out1 = (batch < B_X)
        ? (g_kvin + (size_t)(batch * CHUNK + N_KV + q) * DMODEL) : nullptr;
    ln_row(lat + (size_t)row * DMODEL, g, b,
           g_latn + (size_t)row * DMODEL, out1);
}

// ---------------- bf16x3 tensor-core GEMM ----------------
// C[M,N] = A[M,K] @ B[K,N], fp32 in/out, internally hi/lo bf16 split with
// 3 mma planes (hi*hi + hi*lo + lo*hi). N % 128 == 0, K % 32 == 0, M guarded.
#define GBM 128
#define GBN 128
#define GBK 32
#define PA  40    // A smem row pitch in bf16 (80B -> LDSM conflict-free)
#define PB  136   // B smem row pitch in bf16 (272B -> LDSM conflict-free)

__device__ __forceinline__ unsigned bf2pack(float lo, float hi) {
    __nv_bfloat162 h = __floats2bfloat162_rn(lo, hi);
    return *(unsigned*)&h;
}

__device__ __forceinline__ void ldsm4(unsigned r[4], const void* p) {
    unsigned a = (unsigned)__cvta_generic_to_shared(p);
    asm volatile("ldmatrix.sync.aligned.m8n8.x4.shared.b16 {%0,%1,%2,%3}, [%4];"
                 : "=r"(r[0]), "=r"(r[1]), "=r"(r[2]), "=r"(r[3]) : "r"(a));
}
__device__ __forceinline__ void ldsm4t(unsigned r[4], const void* p) {
    unsigned a = (unsigned)__cvta_generic_to_shared(p);
    asm volatile("ldmatrix.sync.aligned.m8n8.x4.trans.shared.b16 {%0,%1,%2,%3}, [%4];"
                 : "=r"(r[0]), "=r"(r[1]), "=r"(r[2]), "=r"(r[3]) : "r"(a));
}
__device__ __forceinline__ void mma16816(float c[4], const unsigned a[4],
                                         unsigned b0, unsigned b1) {
    asm volatile(
        "mma.sync.aligned.m16n8k16.row.col.f32.bf16.bf16.f32 "
        "{%0,%1,%2,%3},{%4,%5,%6,%7},{%8,%9},{%0,%1,%2,%3};"
        : "+f"(c[0]), "+f"(c[1]), "+f"(c[2]), "+f"(c[3])
        : "r"(a[0]), "r"(a[1]), "r"(a[2]), "r"(a[3]), "r"(b0), "r"(b1));
}

__global__ __launch_bounds__(256) void gemm_bf16x3_kernel(
        const float* __restrict__ A, const float* __restrict__ B,
        float* __restrict__ C, int M, int N, int K) {
    __shared__ __align__(16) __nv_bfloat16 sAhi[GBM * PA];
    __shared__ __align__(16) __nv_bfloat16 sAlo[GBM * PA];
    __shared__ __align__(16) __nv_bfloat16 sBhi[GBK * PB];
    __shared__ __align__(16) __nv_bfloat16 sBlo[GBK * PB];

    int t = threadIdx.x;
    int lane = t & 31, w = t >> 5;
    int wm = w >> 1, wn = w & 1;           // 4 x 2 warp grid
    int m_blk = blockIdx.y * GBM;
    int n_blk = blockIdx.x * GBN;

    float c[2][8][4];
    #pragma unroll
    for (int mt = 0; mt < 2; mt++)
        #pragma unroll
        for (int nt = 0; nt < 8; nt++)
            #pragma unroll
            for (int i = 0; i < 4; i++) c[mt][nt][i] = 0.f;

    // per-thread gmem tile coords
    int am  = t >> 3;            // 0..31, A row stride 32 per i
    int ak4 = t & 7;             // float4 col in A tile
    int bk  = t >> 5;            // 0..7, B k-row stride 8 per i
    int bn4 = t & 31;            // float4 col in B tile

    float4 ra[4], rb[4];
    #pragma unroll
    for (int i = 0; i < 4; i++) {
        int gm = m_blk + am + 32 * i;
        ra[i] = (gm < M) ? *(const float4*)(A + (size_t)gm * K + 4 * ak4)
                         : make_float4(0.f, 0.f, 0.f, 0.f);
        rb[i] = *(const float4*)(B + (size_t)(bk + 8 * i) * N + n_blk + 4 * bn4);
    }

    // lane-derived ldmatrix row selectors
    int l7  = lane & 7;
    int l8  = (lane >> 3) & 1;
    int l16 = lane >> 4;

    for (int k0 = 0; k0 < K; k0 += GBK) {
        // ---- stage smem (hi/lo split) ----
        #pragma unroll
        for (int i = 0; i < 4; i++) {
            float4 v = ra[i];
            __nv_bfloat16 hx = __float2bfloat16_rn(v.x);
            __nv_bfloat16 hy = __float2bfloat16_rn(v.y);
            __nv_bfloat16 hz = __float2bfloat16_rn(v.z);
            __nv_bfloat16 hw = __float2bfloat16_rn(v.w);
            int sa = (am + 32 * i) * PA + 4 * ak4;
            *(unsigned*)&sAhi[sa]     = bf2pack(__bfloat162float(hx), __bfloat162float(hy));
            *(unsigned*)&sAhi[sa + 2] = bf2pack(__bfloat162float(hz), __bfloat162float(hw));
            *(unsigned*)&sAlo[sa]     = bf2pack(v.x - __bfloat162float(hx), v.y - __bfloat162float(hy));
            *(unsigned*)&sAlo[sa + 2] = bf2pack(v.z - __bfloat162float(hz), v.w - __bfloat162float(hw));

            v = rb[i];
            hx = __float2bfloat16_rn(v.x); hy = __float2bfloat16_rn(v.y);
            hz = __float2bfloat16_rn(v.z); hw = __float2bfloat16_rn(v.w);
            int sb = (bk + 8 * i) * PB + 4 * bn4;
            *(unsigned*)&sBhi[sb]     = bf2pack(__bfloat162float(hx), __bfloat162float(hy));
            *(unsigned*)&sBhi[sb + 2] = bf2pack(__bfloat162float(hz), __bfloat162float(hw));
            *(unsigned*)&sBlo[sb]     = bf2pack(v.x - __bfloat162float(hx), v.y - __bfloat162float(hy));
            *(unsigned*)&sBlo[sb + 2] = bf2pack(v.z - __bfloat162float(hz), v.w - __bfloat162float(hw));
        }
        __syncthreads();

        // ---- prefetch next k-block into registers ----
        if (k0 + GBK < K) {
            #pragma unroll
            for (int i = 0; i < 4; i++) {
                int gm = m_blk + am + 32 * i;
                ra[i] = (gm < M) ? *(const float4*)(A + (size_t)gm * K + k0 + GBK + 4 * ak4)
                                 : make_float4(0.f, 0.f, 0.f, 0.f);
                rb[i] = *(const float4*)(B + (size_t)(k0 + GBK + bk + 8 * i) * N + n_blk + 4 * bn4);
            }
        }

        // ---- compute: two k16 steps ----
        #pragma unroll
        for (int ks = 0; ks < GBK; ks += 16) {
            unsigned ah[2][4], al[2][4];
            #pragma unroll
            for (int mt = 0; mt < 2; mt++) {
                int row = wm * 32 + mt * 16 + l7 + 8 * l8;
                int kc  = ks + 8 * l16;
                ldsm4(ah[mt], &sAhi[row * PA + kc]);
                ldsm4(al[mt], &sAlo[row * PA + kc]);
            }
            unsigned bh[4][4], bl[4][4];
            #pragma unroll
            for (int ng = 0; ng < 4; ng++) {
                int krow = ks + l7 + 8 * l8;
                int ncol = wn * 64 + ng * 16 + 8 * l16;
                ldsm4t(bh[ng], &sBhi[krow * PB + ncol]);
                ldsm4t(bl[ng], &sBlo[krow * PB + ncol]);
            }
            #pragma unroll
            for (int mt = 0; mt < 2; mt++)
                #pragma unroll
                for (int nt = 0; nt < 8; nt++) {
                    int ng = nt >> 1, hf = (nt & 1) << 1;
                    mma16816(c[mt][nt], ah[mt], bh[ng][hf], bh[ng][hf + 1]);
                    mma16816(c[mt][nt], ah[mt], bl[ng][hf], bl[ng][hf + 1]);
                    mma16816(c[mt][nt], al[mt], bh[ng][hf], bh[ng][hf + 1]);
                }
        }
        __syncthreads();
    }

    // ---- epilogue ----
    int g = lane >> 2, tig = lane & 3;
    #pragma unroll
    for (int mt = 0; mt < 2; mt++)
        #pragma unroll
        for (int nt = 0; nt < 8; nt++) {
            int r0  = m_blk + wm * 32 + mt * 16 + g;
            int col = n_blk + wn * 64 + nt * 8 + 2 * tig;
            if (r0 < M)
                *(float2*)(C + (size_t)r0 * N + col) =
                    make_float2(c[mt][nt][0], c[mt][nt][1]);
            if (r0 + 8 < M)
                *(float2*)(C + (size_t)(r0 + 8) * N + col) =
                    make_float2(c[mt][nt][2], c[mt][nt][3]);
        }
}

// ---------------- attention ----------------
// grid: (16 jobs, 16 heads). job<8: diagonal block (q-batch j, kv-chunk j), writes
// normalized output. job>=8: split-KV chunk (j-8) for q-batch 8, writes partials.
// 256 threads = 8 warps; warp w owns query rows w*8..w*8+7.
__global__ __launch_bounds__(256) void attn_kernel() {
    extern __shared__ float sm[];
    float* Qs = sm;                      // 64*64
    float* Ks = Qs + 64 * 64;            // 64*68 (padded)
    float* Vs = Ks + 64 * 68;            // 64*64
    float* Ps = Vs + 64 * 64;            // 64*64

    int job = blockIdx.x;
    int h   = blockIdx.y;
    int t = threadIdx.x;
    int lane = t & 31, w = t >> 5;
    bool diag = (job < 8);
    int qb = diag ? job : 8;
    int kc = diag ? job : (job - 8);

    // load Q tile (pre-scaled)
    for (int i = t; i < 64 * 16; i += 256) {
        int r = i >> 4, c4 = (i & 15) << 2;
        float4 v = *(const float4*)(g_Q + (size_t)(qb * 64 + r) * DMODEL + h * DH + c4);
        v.x *= SCALE; v.y *= SCALE; v.z *= SCALE; v.w *= SCALE;
        *(float4*)&Qs[r * 64 + c4] = v;
    }

    float m[8], l[8], o0[8], o1[8];
    #pragma unroll
    for (int rr = 0; rr < 8; rr++) { m[rr] = -INFINITY; l[rr] = 0.f; o0[rr] = 0.f; o1[rr] = 0.f; }

    for (int tt = 0; tt < CHUNK / 64; tt++) {          // 5 key tiles of 64
        int base = kc * CHUNK + tt * 64;
        // load K (padded rows) and V
        for (int i = t; i < 64 * 16; i += 256) {
            int r = i >> 4, c4 = (i & 15) << 2;
            const float* src = g_KV + (size_t)(base + r) * (2 * DMODEL) + h * DH;
            float4 kk = *(const float4*)(src + c4);
            *(float4*)&Ks[r * 68 + c4] = kk;
            float4 vv = *(const float4*)(src + DMODEL + c4);
            *(float4*)&Vs[r * 64 + c4] = vv;
        }
        __syncthreads();

        // scores: s[rr] for keys (lane, lane+32), K held in regs across rows
        float s0[8], s1[8];
        #pragma unroll
        for (int rr = 0; rr < 8; rr++) { s0[rr] = 0.f; s1[rr] = 0.f; }
        const float* k0p = &Ks[lane * 68];
        const float* k1p = &Ks[(lane + 32) * 68];
        #pragma unroll
        for (int d4 = 0; d4 < 16; d4++) {
            float4 ka = *(const float4*)(k0p + d4 * 4);
            float4 kb = *(const float4*)(k1p + d4 * 4);
            #pragma unroll
            for (int rr = 0; rr < 8; rr++) {
                float4 q4 = *(const float4*)&Qs[(w * 8 + rr) * 64 + d4 * 4];
                s0[rr] = fmaf(q4.x, ka.x, s0[rr]); s0[rr] = fmaf(q4.y, ka.y, s0[rr]);
                s0[rr] = fmaf(q4.z, ka.z, s0[rr]); s0[rr] = fmaf(q4.w, ka.w, s0[rr]);
                s1[rr] = fmaf(q4.x, kb.x, s1[rr]); s1[rr] = fmaf(q4.y, kb.y, s1[rr]);
                s1[rr] = fmaf(q4.z, kb.z, s1[rr]); s1[rr] = fmaf(q4.w, kb.w, s1[rr]);
            }
        }

        // online softmax update per row
        #pragma unroll
        for (int rr = 0; rr < 8; rr++) {
            int r = w * 8 + rr;
            float mt = fmaxf(s0[rr], s1[rr]);
            #pragma unroll
            for (int o = 16; o; o >>= 1) mt = fmaxf(mt, __shfl_xor_sync(0xffffffffu, mt, o));
            float mn = fmaxf(m[rr], mt);
            float corr = __expf(m[rr] - mn);
            float p0 = __expf(s0[rr] - mn);
            float p1 = __expf(s1[rr] - mn);
            Ps[r * 64 + lane]      = p0;
            Ps[r * 64 + lane + 32] = p1;
            float ps = p0 + p1;
            #pragma unroll
            for (int o = 16; o; o >>= 1) ps += __shfl_xor_sync(0xffffffffu, ps, o);
            l[rr] = l[rr] * corr + ps;
            m[rr] = mn;
            o0[rr] *= corr;
            o1[rr] *= corr;
        }
        __syncwarp();

        // PV: V held in regs across rows, P read as float4 broadcast
        #pragma unroll
        for (int k4 = 0; k4 < 16; k4++) {
            float va[4], vb[4];
            #pragma unroll
            for (int kk = 0; kk < 4; kk++) {
                va[kk] = Vs[(k4 * 4 + kk) * 64 + lane];
                vb[kk] = Vs[(k4 * 4 + kk) * 64 + lane + 32];
            }
            #pragma unroll
            for (int rr = 0; rr < 8; rr++) {
                float4 p4 = *(const float4*)&Ps[(w * 8 + rr) * 64 + k4 * 4];
                o0[rr] = fmaf(p4.x, va[0], o0[rr]); o0[rr] = fmaf(p4.y, va[1], o0[rr]);
                o0[rr] = fmaf(p4.z, va[2], o0[rr]); o0[rr] = fmaf(p4.w, va[3], o0[rr]);
                o1[rr] = fmaf(p4.x, vb[0], o1[rr]); o1[rr] = fmaf(p4.y, vb[1], o1[rr]);
                o1[rr] = fmaf(p4.z, vb[2], o1[rr]); o1[rr] = fmaf(p4.w, vb[3], o1[rr]);
            }
        }
        __syncthreads();
    }

    if (diag) {
        #pragma unroll
        for (int rr = 0; rr < 8; rr++) {
            int r = w * 8 + rr;
            float inv = 1.f / l[rr];
            float* dst = g_attn + (size_t)(qb * 64 + r) * DMODEL + h * DH;
            dst[lane]      = o0[rr] * inv;
            dst[lane + 32] = o1[rr] * inv;
        }
    } else {
        #pragma unroll
        for (int rr = 0; rr < 8; rr++) {
            int r = w * 8 + rr;
            float* dst = g_Po + (size_t)((kc * HEADS + h) * N_Q + r) * DH;
            dst[lane]      = o0[rr];
            dst[lane + 32] = o1[rr];
            if (lane == 0) {
                g_Pm[(kc * HEADS + h) * N_Q + r] = m[rr];
                g_Pl[(kc * HEADS + h) * N_Q + r] = l[rr];
            }
        }
    }
}

// combine split-KV partials for batch 8. grid (16 heads, 64 rows), 64 threads.
__global__ __launch_bounds__(64) void attn_reduce_kernel() {
    int h = blockIdx.x, r = blockIdx.y, d = threadIdx.x;
    float mx = -INFINITY;
    #pragma unroll
    for (int c = 0; c < 8; c++)
        mx = fmaxf(mx, g_Pm[(c * HEADS + h) * N_Q + r]);
    float lsum = 0.f, acc = 0.f;
    #pragma unroll
    for (int c = 0; c < 8; c++) {
        float wgt = __expf(g_Pm[(c * HEADS + h) * N_Q + r] - mx);
        lsum += g_Pl[(c * HEADS + h) * N_Q + r] * wgt;
        acc = fmaf(g_Po[(size_t)((c * HEADS + h) * N_Q + r) * DH + d], wgt, acc);
    }
    g_attn[(size_t)(8 * 64 + r) * DMODEL + h * DH + d] = acc / lsum;
}

// ---------------- launch ----------------
extern "C" void kernel_launch(void* const* d_in, const int* in_sizes, int n_in,
                              void* d_out, int out_size) {
    const float* x    = (const float*)d_in[0];
    const float* lat  = (const float*)d_in[1];
    const float* g1   = (const float*)d_in[2];
    const float* b1   = (const float*)d_in[3];
    const float* g2   = (const float*)d_in[4];
    const float* b2   = (const float*)d_in[5];
    const float* Wq   = (const float*)d_in[6];
    const float* Wkv  = (const float*)d_in[7];
    const float* Wout = (const float*)d_in[8];
    float* out = (float*)d_out;

    void *p_latn, *p_kvin, *p_Q, *p_KV, *p_attn;
    cudaGetSymbolAddress(&p_latn, g_latn);
    cudaGetSymbolAddress(&p_kvin, g_kvin);
    cudaGetSymbolAddress(&p_Q,    g_Q);
    cudaGetSymbolAddress(&p_KV,   g_KV);
    cudaGetSymbolAddress(&p_attn, g_attn);

    int attn_smem = (64 * 64 + 64 * 68 + 64 * 64 + 64 * 64) * (int)sizeof(float);
    cudaFuncSetAttribute(attn_kernel, cudaFuncAttributeMaxDynamicSharedMemorySize, attn_smem);

    ln_x_kernel<<<B_X * N_KV, 256>>>(x, g1, b1);
    ln_lat_kernel<<<Q_ROWS, 256>>>(lat, g2, b2);

    // Q = latn @ Wq : (576 x 1024) @ (1024 x 1024)
    gemm_bf16x3_kernel<<<dim3(DMODEL / GBN, (Q_ROWS + GBM - 1) / GBM), 256>>>(
        (const float*)p_latn, Wq, (float*)p_Q, Q_ROWS, DMODEL, DMODEL);

    // KV = kvin @ Wkv : (2560 x 1024) @ (1024 x 2048)
    gemm_bf16x3_kernel<<<dim3(2 * DMODEL / GBN, KV_ROWS / GBM), 256>>>(
        (const float*)p_kvin, Wkv, (float*)p_KV, KV_ROWS, 2 * DMODEL, DMODEL);

    attn_kernel<<<dim3(16, HEADS), 256, attn_smem>>>();
    attn_reduce_kernel<<<dim3(HEADS, N_Q), 64>>>();

    // out = attn @ Wout : (576 x 1024) @ (1024 x 1024)
    gemm_bf16x3_kernel<<<dim3(DMODEL / GBN, (Q_ROWS + GBM - 1) / GBM), 256>>>(
        (const float*)p_attn, Wout, out, Q_ROWS, DMODEL, DMODEL);

    (void)in_sizes; (void)n_in; (void)out_size;
}